// round 2
// baseline (speedup 1.0000x reference)
#include <cuda_runtime.h>
#include <cstdint>

// Problem dims (fixed by reference)
#define NB 32
#define NT 128
#define NS 64
#define NF 256
#define MROWS (NB*NT*NS)   // 262144 rows of x flattened as [M, F]

// Scratch (device globals: allocation-free rule)
__device__ float g_uit[(size_t)MROWS * NF];  // 256 MiB: x @ W
__device__ float g_xwl[MROWS];               // x @ W_l

// =====================================================================
// Kernel 1: uit = x @ W  (M=262144, K=256, N=256), fused xwl = x @ W_l
// SIMT GEMM, packed f32x2 FMA (FFMA2). BM=128, BN=256(full), BK=16,
// 512 threads, 8x8 microtile per thread.
// =====================================================================
__global__ void __launch_bounds__(512, 1)
gemm_uit_kernel(const float* __restrict__ x,
                const float* __restrict__ W,
                const float* __restrict__ Wl)
{
    __shared__ float As[16][132];   // transposed A tile, padded
    __shared__ float Bs[16][256];

    const int tid = threadIdx.x;
    const int m0  = blockIdx.x * 128;
    const int tx  = tid & 31;       // n-tile index (32 * 8 = 256)
    const int ty  = tid >> 5;       // m-tile index (16 * 8 = 128)
    const int mb  = ty * 8;
    const int nb  = tx * 8;

    unsigned long long acc[8][4];
    #pragma unroll
    for (int i = 0; i < 8; i++)
        #pragma unroll
        for (int j = 0; j < 4; j++) acc[i][j] = 0ULL;

    float xl = 0.0f;  // x @ W_l accumulator (threads 0..127, row = tid)

    for (int k0 = 0; k0 < 256; k0 += 16) {
        // --- load A tile (128 x 16) transposed into As[k][m] ---
        {
            int row = tid >> 2;           // 0..127
            int c4  = (tid & 3) * 4;      // 0,4,8,12
            float4 v = *reinterpret_cast<const float4*>(
                &x[(size_t)(m0 + row) * 256 + k0 + c4]);
            As[c4 + 0][row] = v.x;
            As[c4 + 1][row] = v.y;
            As[c4 + 2][row] = v.z;
            As[c4 + 3][row] = v.w;
        }
        // --- load B tile (16 x 256) ---
        #pragma unroll
        for (int p = 0; p < 2; p++) {
            int fid = tid + p * 512;
            int row = fid >> 6;           // 0..15
            int col = (fid & 63) * 4;
            float4 v = *reinterpret_cast<const float4*>(
                &W[(size_t)(k0 + row) * 256 + col]);
            *reinterpret_cast<float4*>(&Bs[row][col]) = v;
        }
        __syncthreads();

        #pragma unroll
        for (int kk = 0; kk < 16; kk++) {
            float4 a0 = *reinterpret_cast<const float4*>(&As[kk][mb]);
            float4 a1 = *reinterpret_cast<const float4*>(&As[kk][mb + 4]);
            ulonglong2 b01 = *reinterpret_cast<const ulonglong2*>(&Bs[kk][nb]);
            ulonglong2 b23 = *reinterpret_cast<const ulonglong2*>(&Bs[kk][nb + 4]);
            float av[8] = {a0.x, a0.y, a0.z, a0.w, a1.x, a1.y, a1.z, a1.w};
            unsigned long long bv[4] = {b01.x, b01.y, b23.x, b23.y};
            #pragma unroll
            for (int i = 0; i < 8; i++) {
                unsigned long long a2;
                asm("mov.b64 %0, {%1, %1};" : "=l"(a2) : "f"(av[i]));
                #pragma unroll
                for (int j = 0; j < 4; j++) {
                    asm("fma.rn.f32x2 %0, %1, %2, %0;"
                        : "+l"(acc[i][j]) : "l"(a2), "l"(bv[j]));
                }
            }
        }
        // fused xwl (one thread per row, warps 0..3)
        if (tid < 128) {
            #pragma unroll
            for (int kk = 0; kk < 16; kk++)
                xl = fmaf(As[kk][tid], Wl[k0 + kk], xl);
        }
        __syncthreads();
    }

    // --- write C ---
    #pragma unroll
    for (int i = 0; i < 8; i++) {
        size_t row = (size_t)(m0 + mb + i);
        float2 p0 = *reinterpret_cast<float2*>(&acc[i][0]);
        float2 p1 = *reinterpret_cast<float2*>(&acc[i][1]);
        float2 p2 = *reinterpret_cast<float2*>(&acc[i][2]);
        float2 p3 = *reinterpret_cast<float2*>(&acc[i][3]);
        float4 o0 = make_float4(p0.x, p0.y, p1.x, p1.y);
        float4 o1 = make_float4(p2.x, p2.y, p3.x, p3.y);
        *reinterpret_cast<float4*>(&g_uit[row * 256 + nb])     = o0;
        *reinterpret_cast<float4*>(&g_uit[row * 256 + nb + 4]) = o1;
    }
    if (tid < 128) g_xwl[m0 + tid] = xl;
}

// =====================================================================
// Kernel 2: sequential scan over T. One CTA per batch element b.
// 512 threads. W_context rows [0..WCF) cached in SMEM.
// =====================================================================
#define WCF 208   // W_context rows resident in shared memory

__global__ void __launch_bounds__(512, 1)
scan_kernel(const float* __restrict__ x,
            const float* __restrict__ Wc,
            const float* __restrict__ Wlc,
            const float* __restrict__ blp,
            const float* __restrict__ bias,
            const float* __restrict__ u,
            float* __restrict__ out)
{
    extern __shared__ float sm[];
    float* wc    = sm;                 // WCF*256
    float* cpart = wc + WCF * 256;     // 512
    float* ctx   = cpart + 512;        // 256
    float* cvec  = ctx + 256;          // 256
    float* sbias = cvec + 256;         // 256
    float* su    = sbias + 256;        // 256
    float* swlc  = su + 256;           // 256
    float* sl    = swlc + 256;         // 64
    float* se    = sl + 64;            // 64
    float* sa    = se + 64;            // 64
    float* red   = sa + 64;            // 32
    float* attp  = red + 32;           // 512
    float* scal  = attp + 512;         // 8

    const int tid  = threadIdx.x;
    const int b    = blockIdx.x;
    const int lane = tid & 31;
    const int wid  = tid >> 5;

    // Preload W_context[0:WCF][:] into SMEM (coalesced float4)
    for (int i = tid; i < WCF * 256 / 4; i += 512)
        reinterpret_cast<float4*>(wc)[i] =
            reinterpret_cast<const float4*>(Wc)[i];
    if (tid < 256) {
        ctx[tid]   = 0.0f;
        sbias[tid] = bias[tid];
        su[tid]    = u[tid];
        swlc[tid]  = Wlc[tid];
    }
    const float bl0 = blp[0];

    float* outO = out;                              // [B,T,F] attended
    float* outC = out + (size_t)NB * NT * NF;       // [B,T,F] context
    float* outW = out + (size_t)2 * NB * NT * NF;   // [B,T,S] weights
    __syncthreads();

    for (int t = 0; t < NT; t++) {
        const int bt = b * NT + t;
        const float* uit_t = g_uit + (size_t)bt * NS * NF;
        const float* x_t   = x     + (size_t)bt * NS * NF;

        // (A) gate-context dot partials + c partials
        float gp = 0.0f;
        if (tid < 256) gp = ctx[tid] * swlc[tid];
        #pragma unroll
        for (int o = 16; o > 0; o >>= 1)
            gp += __shfl_down_sync(0xffffffffu, gp, o);
        if (wid < 8 && lane == 0) red[wid] = gp;
        {
            int g = tid & 255, h = tid >> 8;
            float s = 0.0f;
            if (h == 0) {
                #pragma unroll 4
                for (int f = 0; f < 128; f++)
                    s = fmaf(ctx[f], wc[f * 256 + g], s);
            } else {
                #pragma unroll 4
                for (int f = 128; f < WCF; f++)
                    s = fmaf(ctx[f], wc[f * 256 + g], s);
                #pragma unroll 4
                for (int f = WCF; f < 256; f++)
                    s = fmaf(ctx[f], __ldg(&Wc[(size_t)f * 256 + g]), s);
            }
            cpart[h * 256 + g] = s;
        }
        __syncthreads();

        // (B) gates l[s] (threads 0..63) and c combine (threads 256..511)
        if (tid < 64) {
            float gctx = 0.0f;
            #pragma unroll
            for (int i = 0; i < 8; i++) gctx += red[i];
            float lg = gctx + bl0 + g_xwl[(size_t)bt * 64 + tid];
            sl[tid] = 1.0f / (1.0f + __expf(-lg));
        } else if (tid >= 256) {
            int g = tid - 256;
            cvec[g] = cpart[g] + cpart[256 + g];
        }
        __syncthreads();

        // (D) tanh + ait dot + exp. 16 warps x 4 sentences each.
        #pragma unroll
        for (int q = 0; q < 4; q++) {
            int s = wid + q * 16;
            float l = sl[s], oml = 1.0f - l;
            float acc = 0.0f;
            #pragma unroll
            for (int i = 0; i < 8; i++) {
                int f = lane + i * 32;
                float arg = fmaf(l, uit_t[s * 256 + f],
                                 fmaf(oml, cvec[f], sbias[f]));
                // tanh(x) = 1 - 2/(exp(2x)+1)   (EX2+RCP path, ~1e-6 err)
                float e2 = __expf(2.0f * arg);
                float th = 1.0f - __fdividef(2.0f, e2 + 1.0f);
                acc = fmaf(th, su[f], acc);
            }
            #pragma unroll
            for (int o = 16; o > 0; o >>= 1)
                acc += __shfl_down_sync(0xffffffffu, acc, o);
            if (lane == 0) se[s] = __expf(acc);
        }
        __syncthreads();

        // (E) softmax denominator
        if (tid < 32) {
            float v = se[tid] + se[tid + 32];
            #pragma unroll
            for (int o = 16; o > 0; o >>= 1)
                v += __shfl_down_sync(0xffffffffu, v, o);
            if (tid == 0) scal[0] = 1.0f / (v + 1e-7f);
        }
        __syncthreads();

        // (F1) normalized weights
        if (tid < 64) {
            float a = se[tid] * scal[0];
            sa[tid] = a;
            outW[(size_t)bt * 64 + tid] = a;
        }
        __syncthreads();

        // (F2) attended partials: attended[f] = sum_s a[s]*x[s,f]
        {
            int f = tid & 255, h = tid >> 8;
            float s = 0.0f;
            #pragma unroll 4
            for (int si = h * 32; si < h * 32 + 32; si++)
                s = fmaf(sa[si], x_t[si * 256 + f], s);
            attp[h * 256 + f] = s;
        }
        __syncthreads();

        // (F3) combine, context update, outputs
        if (tid < 256) {
            float att = attp[tid] + attp[256 + tid];
            float nc  = ctx[tid] + att;          // DISCOUNT = 1
            ctx[tid]  = nc;
            outO[(size_t)bt * 256 + tid] = att;
            outC[(size_t)bt * 256 + tid] = nc;
        }
        __syncthreads();
    }
}

// =====================================================================
// Launch
// =====================================================================
extern "C" void kernel_launch(void* const* d_in, const int* in_sizes, int n_in,
                              void* d_out, int out_size)
{
    const float* x   = (const float*)d_in[0];  // [B,T,S,F]
    const float* W   = (const float*)d_in[1];  // [F,F]
    const float* Wc  = (const float*)d_in[2];  // [F,F]
    const float* Wl  = (const float*)d_in[3];  // [F]
    const float* Wlc = (const float*)d_in[4];  // [F]
    const float* bl  = (const float*)d_in[5];  // [1]
    const float* bb  = (const float*)d_in[6];  // [F]
    const float* u   = (const float*)d_in[7];  // [F]
    float* out = (float*)d_out;

    // 1) hoisted GEMM: uit = x @ W (+ fused xwl = x @ W_l)
    gemm_uit_kernel<<<MROWS / 128, 512>>>(x, W, Wl);

    // 2) sequential scan, one CTA per batch element
    const size_t smem_bytes =
        (size_t)(WCF * 256 + 512 + 256 * 5 + 64 * 3 + 32 + 512 + 8) * sizeof(float);
    cudaFuncSetAttribute(scan_kernel,
                         cudaFuncAttributeMaxDynamicSharedMemorySize,
                         (int)smem_bytes);
    scan_kernel<<<NB, 512, smem_bytes>>>(x, Wc, Wlc, bl, bb, u, out);
}

// round 3
// speedup vs baseline: 1.7922x; 1.7922x over previous
#include <cuda_runtime.h>
#include <cstdint>

// Problem dims (fixed by reference)
#define NB 32
#define NT 128
#define NS 64
#define NF 256
#define MROWS (NB*NT*NS)   // 262144 rows of x flattened as [M, F]

// Scratch (device globals: allocation-free rule)
__device__ float g_uit[(size_t)MROWS * NF];  // 256 MiB: x @ W
__device__ float g_xwl[MROWS];               // x @ W_l

// =====================================================================
// Kernel 1: uit = x @ W  (M=262144, K=256, N=256), fused xwl = x @ W_l
// SIMT GEMM, packed f32x2 FMA (FFMA2). BM=128, BN=256(full), BK=16,
// 512 threads, 8x8 microtile per thread.  (unchanged from R2)
// =====================================================================
__global__ void __launch_bounds__(512, 1)
gemm_uit_kernel(const float* __restrict__ x,
                const float* __restrict__ W,
                const float* __restrict__ Wl)
{
    __shared__ float As[16][132];   // transposed A tile, padded
    __shared__ float Bs[16][256];

    const int tid = threadIdx.x;
    const int m0  = blockIdx.x * 128;
    const int tx  = tid & 31;       // n-tile index (32 * 8 = 256)
    const int ty  = tid >> 5;       // m-tile index (16 * 8 = 128)
    const int mb  = ty * 8;
    const int nb  = tx * 8;

    unsigned long long acc[8][4];
    #pragma unroll
    for (int i = 0; i < 8; i++)
        #pragma unroll
        for (int j = 0; j < 4; j++) acc[i][j] = 0ULL;

    float xl = 0.0f;  // x @ W_l accumulator (threads 0..127, row = tid)

    for (int k0 = 0; k0 < 256; k0 += 16) {
        {
            int row = tid >> 2;           // 0..127
            int c4  = (tid & 3) * 4;      // 0,4,8,12
            float4 v = *reinterpret_cast<const float4*>(
                &x[(size_t)(m0 + row) * 256 + k0 + c4]);
            As[c4 + 0][row] = v.x;
            As[c4 + 1][row] = v.y;
            As[c4 + 2][row] = v.z;
            As[c4 + 3][row] = v.w;
        }
        #pragma unroll
        for (int p = 0; p < 2; p++) {
            int fid = tid + p * 512;
            int row = fid >> 6;           // 0..15
            int col = (fid & 63) * 4;
            float4 v = *reinterpret_cast<const float4*>(
                &W[(size_t)(k0 + row) * 256 + col]);
            *reinterpret_cast<float4*>(&Bs[row][col]) = v;
        }
        __syncthreads();

        #pragma unroll
        for (int kk = 0; kk < 16; kk++) {
            float4 a0 = *reinterpret_cast<const float4*>(&As[kk][mb]);
            float4 a1 = *reinterpret_cast<const float4*>(&As[kk][mb + 4]);
            ulonglong2 b01 = *reinterpret_cast<const ulonglong2*>(&Bs[kk][nb]);
            ulonglong2 b23 = *reinterpret_cast<const ulonglong2*>(&Bs[kk][nb + 4]);
            float av[8] = {a0.x, a0.y, a0.z, a0.w, a1.x, a1.y, a1.z, a1.w};
            unsigned long long bv[4] = {b01.x, b01.y, b23.x, b23.y};
            #pragma unroll
            for (int i = 0; i < 8; i++) {
                unsigned long long a2;
                asm("mov.b64 %0, {%1, %1};" : "=l"(a2) : "f"(av[i]));
                #pragma unroll
                for (int j = 0; j < 4; j++) {
                    asm("fma.rn.f32x2 %0, %1, %2, %0;"
                        : "+l"(acc[i][j]) : "l"(a2), "l"(bv[j]));
                }
            }
        }
        if (tid < 128) {
            #pragma unroll
            for (int kk = 0; kk < 16; kk++)
                xl = fmaf(As[kk][tid], Wl[k0 + kk], xl);
        }
        __syncthreads();
    }

    #pragma unroll
    for (int i = 0; i < 8; i++) {
        size_t row = (size_t)(m0 + mb + i);
        float2 p0 = *reinterpret_cast<float2*>(&acc[i][0]);
        float2 p1 = *reinterpret_cast<float2*>(&acc[i][1]);
        float2 p2 = *reinterpret_cast<float2*>(&acc[i][2]);
        float2 p3 = *reinterpret_cast<float2*>(&acc[i][3]);
        float4 o0 = make_float4(p0.x, p0.y, p1.x, p1.y);
        float4 o1 = make_float4(p2.x, p2.y, p3.x, p3.y);
        *reinterpret_cast<float4*>(&g_uit[row * 256 + nb])     = o0;
        *reinterpret_cast<float4*>(&g_uit[row * 256 + nb + 4]) = o1;
    }
    if (tid < 128) g_xwl[m0 + tid] = xl;
}

// =====================================================================
// Kernel 2: cluster scan. 4 CTAs per batch element (cluster 4),
// grid = 128 CTAs, 512 threads each.
//   rank r owns: Wc columns [r*64, r*64+64) in SMEM,
//                sentences  [r*16, r*16+16),
//   uit/x tiles double-buffered via cp.async,
//   cross-CTA exchange via DSMEM st.shared::cluster + barrier.cluster.
// =====================================================================

__device__ __forceinline__ uint32_t smem_u32(const void* p) {
    uint32_t a;
    asm("{ .reg .u64 t; cvta.to.shared.u64 t, %1; cvt.u32.u64 %0, t; }"
        : "=r"(a) : "l"(p));
    return a;
}
__device__ __forceinline__ uint32_t mapa_u32(uint32_t a, uint32_t rank) {
    uint32_t o;
    asm("mapa.shared::cluster.u32 %0, %1, %2;" : "=r"(o) : "r"(a), "r"(rank));
    return o;
}
__device__ __forceinline__ void st_remote(uint32_t a, float v) {
    asm volatile("st.shared::cluster.f32 [%0], %1;" :: "r"(a), "f"(v));
}
__device__ __forceinline__ void cp16(uint32_t s, const void* g) {
    asm volatile("cp.async.cg.shared.global [%0], [%1], 16;" :: "r"(s), "l"(g));
}
__device__ __forceinline__ void cluster_sync() {
    asm volatile("barrier.cluster.arrive.aligned;" ::: "memory");
    asm volatile("barrier.cluster.wait.aligned;"   ::: "memory");
}

// SMEM float offsets
#define OFF_WCQ   0
#define OFF_UBUF  16384          // 2 x 4096
#define OFF_XBUF  (OFF_UBUF + 8192)
#define OFF_CTX   (OFF_XBUF + 8192)
#define OFF_CVEC  (OFF_CTX + 256)
#define OFF_BIAS  (OFF_CVEC + 256)
#define OFF_U     (OFF_BIAS + 256)
#define OFF_WLC   (OFF_U + 256)
#define OFF_PART  (OFF_WLC + 256)
#define OFF_ATTP  (OFF_PART + 512)
#define OFF_ATTQ  (OFF_ATTP + 512)   // 4 x 256
#define OFF_SE    (OFF_ATTQ + 1024)
#define OFF_SL    (OFF_SE + 64)
#define OFF_SA    (OFF_SL + 16)
#define SMEM_FLOATS (OFF_SA + 32)

__global__ void __launch_bounds__(512, 1) __cluster_dims__(4, 1, 1)
scan_cluster_kernel(const float* __restrict__ x,
                    const float* __restrict__ Wc,
                    const float* __restrict__ Wlc,
                    const float* __restrict__ blp,
                    const float* __restrict__ bias,
                    const float* __restrict__ u,
                    float* __restrict__ out)
{
    extern __shared__ float sm[];
    float* wcq  = sm + OFF_WCQ;
    float* ubuf = sm + OFF_UBUF;
    float* xbuf = sm + OFF_XBUF;
    float* ctx  = sm + OFF_CTX;
    float* cvec = sm + OFF_CVEC;
    float* sbias= sm + OFF_BIAS;
    float* su   = sm + OFF_U;
    float* swlc = sm + OFF_WLC;
    float* part = sm + OFF_PART;
    float* attp = sm + OFF_ATTP;
    float* attq = sm + OFF_ATTQ;
    float* se   = sm + OFF_SE;
    float* sl   = sm + OFF_SL;
    float* sa   = sm + OFF_SA;

    const int tid  = threadIdx.x;
    const int lane = tid & 31;
    const int wid  = tid >> 5;
    const uint32_t r = (uint32_t)(blockIdx.x & 3);   // cluster rank
    const int b = blockIdx.x >> 2;

    const uint32_t ubuf_a = smem_u32(ubuf);
    const uint32_t xbuf_a = smem_u32(xbuf);
    const uint32_t cvec_a = smem_u32(cvec);
    const uint32_t se_a   = smem_u32(se);
    const uint32_t attq_a = smem_u32(attq);

    // --- init: Wc quarter (columns [r*64, r*64+64)), consts, ctx=0 ---
    for (int i = tid; i < 4096; i += 512) {          // 4096 float4
        int f  = i >> 4;
        int c4 = (i & 15) << 2;
        float4 v = *reinterpret_cast<const float4*>(
            &Wc[(size_t)f * 256 + r * 64 + c4]);
        *reinterpret_cast<float4*>(&wcq[f * 64 + c4]) = v;
    }
    if (tid < 256) {
        ctx[tid]   = 0.0f;
        sbias[tid] = bias[tid];
        su[tid]    = u[tid];
        swlc[tid]  = Wlc[tid];
    }
    const float bl0 = blp[0];

    float* outO = out;
    float* outC = out + (size_t)NB * NT * NF;
    float* outW = out + (size_t)2 * NB * NT * NF;

    // prefetch tile 0 (own 16 sentences of uit and x)
    {
        size_t base = ((size_t)(b * NT) * NS + r * 16) * NF;
        const float4* gu = reinterpret_cast<const float4*>(g_uit + base);
        const float4* gx = reinterpret_cast<const float4*>(x + base);
        for (int i = tid; i < 1024; i += 512) {
            cp16(ubuf_a + i * 16, gu + i);
            cp16(xbuf_a + i * 16, gx + i);
        }
        asm volatile("cp.async.commit_group;");
    }
    __syncthreads();
    cluster_sync();

    for (int t = 0; t < NT; t++) {
        const int bt = b * NT + t;
        const int cur = t & 1;

        // --- prefetch tile t+1 ---
        if (t + 1 < NT) {
            size_t base = ((size_t)(bt + 1) * NS + r * 16) * NF;
            const float4* gu = reinterpret_cast<const float4*>(g_uit + base);
            const float4* gx = reinterpret_cast<const float4*>(x + base);
            uint32_t ub = ubuf_a + (uint32_t)(cur ^ 1) * 16384;
            uint32_t xb = xbuf_a + (uint32_t)(cur ^ 1) * 16384;
            for (int i = tid; i < 1024; i += 512) {
                cp16(ub + i * 16, gu + i);
                cp16(xb + i * 16, gx + i);
            }
        }
        asm volatile("cp.async.commit_group;");

        // xwl loads for gate (warp 2, lanes 0..15)
        float xwl_v = 0.0f;
        if (wid == 2 && lane < 16)
            xwl_v = __ldg(&g_xwl[(size_t)bt * NS + r * 16 + lane]);

        // --- phase 1: matvec partials for own 64 outputs ---
        {
            int g = tid & 63, p = tid >> 6;
            int f0 = p * 32;
            float s0 = 0.0f, s1 = 0.0f;
            #pragma unroll
            for (int i = 0; i < 32; i += 2) {
                s0 = fmaf(ctx[f0 + i],     wcq[(f0 + i) * 64 + g],     s0);
                s1 = fmaf(ctx[f0 + i + 1], wcq[(f0 + i + 1) * 64 + g], s1);
            }
            part[p * 64 + g] = s0 + s1;
        }
        __syncthreads();

        if (tid < 64) {
            float s = 0.0f;
            #pragma unroll
            for (int p = 0; p < 8; p++) s += part[p * 64 + tid];
            cvec[r * 64 + tid] = s;
            uint32_t la = cvec_a + (r * 64 + tid) * 4;
            #pragma unroll
            for (uint32_t q = 0; q < 4; q++)
                if (q != r) st_remote(mapa_u32(la, q), s);
        } else if (wid == 2) {
            // gate: <ctx, Wlc> (+bl +xwl), sigmoid
            float gp = 0.0f;
            #pragma unroll
            for (int i = 0; i < 8; i++)
                gp = fmaf(ctx[lane + i * 32], swlc[lane + i * 32], gp);
            #pragma unroll
            for (int o = 16; o > 0; o >>= 1)
                gp += __shfl_down_sync(0xffffffffu, gp, o);
            gp = __shfl_sync(0xffffffffu, gp, 0);
            if (lane < 16) {
                float lg = gp + bl0 + xwl_v;
                sl[lane] = 1.0f / (1.0f + __expf(-lg));
            }
        }

        asm volatile("cp.async.wait_group 1;");
        cluster_sync();   // cvec + sl visible

        // --- phase 2: tanh + ait + exp, warp w = own sentence w ---
        {
            float l = sl[wid], oml = 1.0f - l;
            const float* ut = ubuf + cur * 4096 + wid * 256;
            float acc = 0.0f;
            #pragma unroll
            for (int i = 0; i < 8; i++) {
                int f = lane + i * 32;
                float arg = fmaf(l, ut[f], fmaf(oml, cvec[f], sbias[f]));
                float e2 = __expf(2.0f * arg);
                float th = 1.0f - __fdividef(2.0f, e2 + 1.0f);
                acc = fmaf(th, su[f], acc);
            }
            #pragma unroll
            for (int o = 16; o > 0; o >>= 1)
                acc += __shfl_down_sync(0xffffffffu, acc, o);
            if (lane == 0) {
                float ev = __expf(acc);
                se[r * 16 + wid] = ev;
                uint32_t la = se_a + (r * 16 + wid) * 4;
                #pragma unroll
                for (uint32_t q = 0; q < 4; q++)
                    if (q != r) st_remote(mapa_u32(la, q), ev);
            }
        }
        cluster_sync();   // full se visible

        // --- phase 3: softmax denom, own a[], attended partials ---
        if (wid == 0) {
            float v = se[lane] + se[lane + 32];
            #pragma unroll
            for (int o = 16; o > 0; o >>= 1)
                v += __shfl_down_sync(0xffffffffu, v, o);
            v = __shfl_sync(0xffffffffu, v, 0);
            float sc = 1.0f / (v + 1e-7f);
            if (lane < 16) {
                float a = se[r * 16 + lane] * sc;
                sa[lane] = a;
                outW[(size_t)bt * 64 + r * 16 + lane] = a;
            }
        }
        __syncthreads();

        {
            int f = tid & 255, h = tid >> 8;
            const float* xt = xbuf + cur * 4096;
            float s = 0.0f;
            #pragma unroll
            for (int j = 0; j < 8; j++)
                s = fmaf(sa[h * 8 + j], xt[(h * 8 + j) * 256 + f], s);
            attp[h * 256 + f] = s;
        }
        __syncthreads();

        if (tid < 256) {
            float a2 = attp[tid] + attp[256 + tid];
            attq[r * 256 + tid] = a2;
            uint32_t la = attq_a + (r * 256 + tid) * 4;
            #pragma unroll
            for (uint32_t q = 0; q < 4; q++)
                if (q != r) st_remote(mapa_u32(la, q), a2);
        }
        cluster_sync();   // all attended partials visible

        // --- phase 4: combine, ctx update, outputs (own f quarter) ---
        if (tid < 256) {
            float att = attq[tid] + attq[256 + tid] +
                        attq[512 + tid] + attq[768 + tid];
            float nc = ctx[tid] + att;      // DISCOUNT = 1
            ctx[tid] = nc;
            if ((uint32_t)(tid >> 6) == r) {
                outO[(size_t)bt * 256 + tid] = att;
                outC[(size_t)bt * 256 + tid] = nc;
            }
        }
        __syncthreads();
    }
}

// =====================================================================
// Launch
// =====================================================================
extern "C" void kernel_launch(void* const* d_in, const int* in_sizes, int n_in,
                              void* d_out, int out_size)
{
    const float* x   = (const float*)d_in[0];  // [B,T,S,F]
    const float* W   = (const float*)d_in[1];  // [F,F]
    const float* Wc  = (const float*)d_in[2];  // [F,F]
    const float* Wl  = (const float*)d_in[3];  // [F]
    const float* Wlc = (const float*)d_in[4];  // [F]
    const float* bl  = (const float*)d_in[5];  // [1]
    const float* bb  = (const float*)d_in[6];  // [F]
    const float* u   = (const float*)d_in[7];  // [F]
    float* out = (float*)d_out;

    // 1) hoisted GEMM: uit = x @ W (+ fused xwl = x @ W_l)
    gemm_uit_kernel<<<MROWS / 128, 512>>>(x, W, Wl);

    // 2) cluster scan: 4 CTAs per batch element
    const size_t smem_bytes = (size_t)SMEM_FLOATS * sizeof(float);
    cudaFuncSetAttribute(scan_cluster_kernel,
                         cudaFuncAttributeMaxDynamicSharedMemorySize,
                         (int)smem_bytes);
    scan_cluster_kernel<<<NB * 4, 512, smem_bytes>>>(x, Wc, Wlc, bl, bb, u, out);
}

// round 4
// speedup vs baseline: 1.8815x; 1.0498x over previous
#include <cuda_runtime.h>
#include <cstdint>

// Problem dims (fixed by reference)
#define NB 32
#define NT 128
#define NS 64
#define NF 256
#define MROWS (NB*NT*NS)   // 262144 rows of x flattened as [M, F]

// Scratch (device globals: allocation-free rule)
__device__ float g_uit[(size_t)MROWS * NF];  // 256 MiB: x @ W
__device__ float g_xwl[MROWS];               // x @ W_l

// =====================================================================
// Kernel 1: uit = x @ W  (M=262144, K=256, N=256), fused xwl = x @ W_l
// SIMT GEMM, packed f32x2 FMA (FFMA2). BM=128, BN=256(full), BK=16,
// 512 threads, 8x8 microtile per thread.  (unchanged from R2)
// =====================================================================
__global__ void __launch_bounds__(512, 1)
gemm_uit_kernel(const float* __restrict__ x,
                const float* __restrict__ W,
                const float* __restrict__ Wl)
{
    __shared__ float As[16][132];   // transposed A tile, padded
    __shared__ float Bs[16][256];

    const int tid = threadIdx.x;
    const int m0  = blockIdx.x * 128;
    const int tx  = tid & 31;       // n-tile index (32 * 8 = 256)
    const int ty  = tid >> 5;       // m-tile index (16 * 8 = 128)
    const int mb  = ty * 8;
    const int nb  = tx * 8;

    unsigned long long acc[8][4];
    #pragma unroll
    for (int i = 0; i < 8; i++)
        #pragma unroll
        for (int j = 0; j < 4; j++) acc[i][j] = 0ULL;

    float xl = 0.0f;  // x @ W_l accumulator (threads 0..127, row = tid)

    for (int k0 = 0; k0 < 256; k0 += 16) {
        {
            int row = tid >> 2;           // 0..127
            int c4  = (tid & 3) * 4;      // 0,4,8,12
            float4 v = *reinterpret_cast<const float4*>(
                &x[(size_t)(m0 + row) * 256 + k0 + c4]);
            As[c4 + 0][row] = v.x;
            As[c4 + 1][row] = v.y;
            As[c4 + 2][row] = v.z;
            As[c4 + 3][row] = v.w;
        }
        #pragma unroll
        for (int p = 0; p < 2; p++) {
            int fid = tid + p * 512;
            int row = fid >> 6;           // 0..15
            int col = (fid & 63) * 4;
            float4 v = *reinterpret_cast<const float4*>(
                &W[(size_t)(k0 + row) * 256 + col]);
            *reinterpret_cast<float4*>(&Bs[row][col]) = v;
        }
        __syncthreads();

        #pragma unroll
        for (int kk = 0; kk < 16; kk++) {
            float4 a0 = *reinterpret_cast<const float4*>(&As[kk][mb]);
            float4 a1 = *reinterpret_cast<const float4*>(&As[kk][mb + 4]);
            ulonglong2 b01 = *reinterpret_cast<const ulonglong2*>(&Bs[kk][nb]);
            ulonglong2 b23 = *reinterpret_cast<const ulonglong2*>(&Bs[kk][nb + 4]);
            float av[8] = {a0.x, a0.y, a0.z, a0.w, a1.x, a1.y, a1.z, a1.w};
            unsigned long long bv[4] = {b01.x, b01.y, b23.x, b23.y};
            #pragma unroll
            for (int i = 0; i < 8; i++) {
                unsigned long long a2;
                asm("mov.b64 %0, {%1, %1};" : "=l"(a2) : "f"(av[i]));
                #pragma unroll
                for (int j = 0; j < 4; j++) {
                    asm("fma.rn.f32x2 %0, %1, %2, %0;"
                        : "+l"(acc[i][j]) : "l"(a2), "l"(bv[j]));
                }
            }
        }
        if (tid < 128) {
            #pragma unroll
            for (int kk = 0; kk < 16; kk++)
                xl = fmaf(As[kk][tid], Wl[k0 + kk], xl);
        }
        __syncthreads();
    }

    #pragma unroll
    for (int i = 0; i < 8; i++) {
        size_t row = (size_t)(m0 + mb + i);
        float2 p0 = *reinterpret_cast<float2*>(&acc[i][0]);
        float2 p1 = *reinterpret_cast<float2*>(&acc[i][1]);
        float2 p2 = *reinterpret_cast<float2*>(&acc[i][2]);
        float2 p3 = *reinterpret_cast<float2*>(&acc[i][3]);
        float4 o0 = make_float4(p0.x, p0.y, p1.x, p1.y);
        float4 o1 = make_float4(p2.x, p2.y, p3.x, p3.y);
        *reinterpret_cast<float4*>(&g_uit[row * 256 + nb])     = o0;
        *reinterpret_cast<float4*>(&g_uit[row * 256 + nb + 4]) = o1;
    }
    if (tid < 128) g_xwl[m0 + tid] = xl;
}

// =====================================================================
// Kernel 2: cluster scan. 4 CTAs per batch element (cluster 4),
// grid = 128 CTAs, 512 threads each.
//   rank r owns: Wc columns [r*64, r*64+64) in SMEM,
//                sentences  [r*16, r*16+16),
//   uit/x tiles double-buffered via cp.async,
//   cross-CTA exchange via DSMEM st.shared::cluster + barrier.cluster.
// =====================================================================

__device__ __forceinline__ uint32_t smem_u32(const void* p) {
    uint32_t a;
    asm("{ .reg .u64 t; cvta.to.shared.u64 t, %1; cvt.u32.u64 %0, t; }"
        : "=r"(a) : "l"(p));
    return a;
}
__device__ __forceinline__ uint32_t mapa_u32(uint32_t a, uint32_t rank) {
    uint32_t o;
    asm("mapa.shared::cluster.u32 %0, %1, %2;" : "=r"(o) : "r"(a), "r"(rank));
    return o;
}
__device__ __forceinline__ void st_remote(uint32_t a, float v) {
    asm volatile("st.shared::cluster.f32 [%0], %1;" :: "r"(a), "f"(v));
}
__device__ __forceinline__ void cp16(uint32_t s, const void* g) {
    asm volatile("cp.async.cg.shared.global [%0], [%1], 16;" :: "r"(s), "l"(g));
}
__device__ __forceinline__ void cluster_sync() {
    asm volatile("barrier.cluster.arrive.aligned;" ::: "memory");
    asm volatile("barrier.cluster.wait.aligned;"   ::: "memory");
}

// SMEM float offsets
#define OFF_WCQ   0
#define OFF_UBUF  16384          // 2 x 4096
#define OFF_XBUF  (OFF_UBUF + 8192)
#define OFF_CTX   (OFF_XBUF + 8192)
#define OFF_CVEC  (OFF_CTX + 256)
#define OFF_BIAS  (OFF_CVEC + 256)
#define OFF_U     (OFF_BIAS + 256)
#define OFF_WLC   (OFF_U + 256)
#define OFF_PART  (OFF_WLC + 256)
#define OFF_ATTP  (OFF_PART + 512)
#define OFF_ATTQ  (OFF_ATTP + 512)   // 4 x 256
#define OFF_SE    (OFF_ATTQ + 1024)
#define OFF_SL    (OFF_SE + 64)
#define OFF_SA    (OFF_SL + 16)
#define SMEM_FLOATS (OFF_SA + 32)

__global__ void __launch_bounds__(512, 1) __cluster_dims__(4, 1, 1)
scan_cluster_kernel(const float* __restrict__ x,
                    const float* __restrict__ Wc,
                    const float* __restrict__ Wlc,
                    const float* __restrict__ blp,
                    const float* __restrict__ bias,
                    const float* __restrict__ u,
                    float* __restrict__ out)
{
    extern __shared__ float sm[];
    float* wcq  = sm + OFF_WCQ;
    float* ubuf = sm + OFF_UBUF;
    float* xbuf = sm + OFF_XBUF;
    float* ctx  = sm + OFF_CTX;
    float* cvec = sm + OFF_CVEC;
    float* sbias= sm + OFF_BIAS;
    float* su   = sm + OFF_U;
    float* swlc = sm + OFF_WLC;
    float* part = sm + OFF_PART;
    float* attp = sm + OFF_ATTP;
    float* attq = sm + OFF_ATTQ;
    float* se   = sm + OFF_SE;
    float* sl   = sm + OFF_SL;
    float* sa   = sm + OFF_SA;

    const int tid  = threadIdx.x;
    const int lane = tid & 31;
    const int wid  = tid >> 5;
    const uint32_t r = (uint32_t)(blockIdx.x & 3);   // cluster rank
    const int b = blockIdx.x >> 2;

    const uint32_t ubuf_a = smem_u32(ubuf);
    const uint32_t xbuf_a = smem_u32(xbuf);
    const uint32_t cvec_a = smem_u32(cvec);
    const uint32_t se_a   = smem_u32(se);
    const uint32_t attq_a = smem_u32(attq);

    // --- init: Wc quarter (columns [r*64, r*64+64)), consts, ctx=0 ---
    for (int i = tid; i < 4096; i += 512) {          // 4096 float4
        int f  = i >> 4;
        int c4 = (i & 15) << 2;
        float4 v = *reinterpret_cast<const float4*>(
            &Wc[(size_t)f * 256 + r * 64 + c4]);
        *reinterpret_cast<float4*>(&wcq[f * 64 + c4]) = v;
    }
    if (tid < 256) {
        ctx[tid]   = 0.0f;
        sbias[tid] = bias[tid];
        su[tid]    = u[tid];
        swlc[tid]  = Wlc[tid];
    }
    const float bl0 = blp[0];

    float* outO = out;
    float* outC = out + (size_t)NB * NT * NF;
    float* outW = out + (size_t)2 * NB * NT * NF;

    // prefetch tile 0 (own 16 sentences of uit and x)
    {
        size_t base = ((size_t)(b * NT) * NS + r * 16) * NF;
        const float4* gu = reinterpret_cast<const float4*>(g_uit + base);
        const float4* gx = reinterpret_cast<const float4*>(x + base);
        for (int i = tid; i < 1024; i += 512) {
            cp16(ubuf_a + i * 16, gu + i);
            cp16(xbuf_a + i * 16, gx + i);
        }
        asm volatile("cp.async.commit_group;");
    }
    __syncthreads();
    cluster_sync();

    for (int t = 0; t < NT; t++) {
        const int bt = b * NT + t;
        const int cur = t & 1;

        // --- prefetch tile t+1 ---
        if (t + 1 < NT) {
            size_t base = ((size_t)(bt + 1) * NS + r * 16) * NF;
            const float4* gu = reinterpret_cast<const float4*>(g_uit + base);
            const float4* gx = reinterpret_cast<const float4*>(x + base);
            uint32_t ub = ubuf_a + (uint32_t)(cur ^ 1) * 16384;
            uint32_t xb = xbuf_a + (uint32_t)(cur ^ 1) * 16384;
            for (int i = tid; i < 1024; i += 512) {
                cp16(ub + i * 16, gu + i);
                cp16(xb + i * 16, gx + i);
            }
        }
        asm volatile("cp.async.commit_group;");

        // xwl loads for gate (warp 2, lanes 0..15)
        float xwl_v = 0.0f;
        if (wid == 2 && lane < 16)
            xwl_v = __ldg(&g_xwl[(size_t)bt * NS + r * 16 + lane]);

        // --- phase 1: matvec partials for own 64 outputs ---
        {
            int g = tid & 63, p = tid >> 6;
            int f0 = p * 32;
            float s0 = 0.0f, s1 = 0.0f;
            #pragma unroll
            for (int i = 0; i < 32; i += 2) {
                s0 = fmaf(ctx[f0 + i],     wcq[(f0 + i) * 64 + g],     s0);
                s1 = fmaf(ctx[f0 + i + 1], wcq[(f0 + i + 1) * 64 + g], s1);
            }
            part[p * 64 + g] = s0 + s1;
        }
        __syncthreads();

        if (tid < 64) {
            float s = 0.0f;
            #pragma unroll
            for (int p = 0; p < 8; p++) s += part[p * 64 + tid];
            cvec[r * 64 + tid] = s;
            uint32_t la = cvec_a + (r * 64 + tid) * 4;
            #pragma unroll
            for (uint32_t q = 0; q < 4; q++)
                if (q != r) st_remote(mapa_u32(la, q), s);
        } else if (wid == 2) {
            // gate: <ctx, Wlc> (+bl +xwl), sigmoid
            float gp = 0.0f;
            #pragma unroll
            for (int i = 0; i < 8; i++)
                gp = fmaf(ctx[lane + i * 32], swlc[lane + i * 32], gp);
            #pragma unroll
            for (int o = 16; o > 0; o >>= 1)
                gp += __shfl_down_sync(0xffffffffu, gp, o);
            gp = __shfl_sync(0xffffffffu, gp, 0);
            if (lane < 16) {
                float lg = gp + bl0 + xwl_v;
                sl[lane] = 1.0f / (1.0f + __expf(-lg));
            }
        }

        asm volatile("cp.async.wait_group 1;");
        cluster_sync();   // cvec + sl visible

        // --- phase 2: tanh + ait + exp, warp w = own sentence w ---
        {
            float l = sl[wid], oml = 1.0f - l;
            const float* ut = ubuf + cur * 4096 + wid * 256;
            float acc = 0.0f;
            #pragma unroll
            for (int i = 0; i < 8; i++) {
                int f = lane + i * 32;
                float arg = fmaf(l, ut[f], fmaf(oml, cvec[f], sbias[f]));
                float e2 = __expf(2.0f * arg);
                float th = 1.0f - __fdividef(2.0f, e2 + 1.0f);
                acc = fmaf(th, su[f], acc);
            }
            #pragma unroll
            for (int o = 16; o > 0; o >>= 1)
                acc += __shfl_down_sync(0xffffffffu, acc, o);
            if (lane == 0) {
                float ev = __expf(acc);
                se[r * 16 + wid] = ev;
                uint32_t la = se_a + (r * 16 + wid) * 4;
                #pragma unroll
                for (uint32_t q = 0; q < 4; q++)
                    if (q != r) st_remote(mapa_u32(la, q), ev);
            }
        }
        cluster_sync();   // full se visible

        // --- phase 3: softmax denom, own a[], attended partials ---
        if (wid == 0) {
            float v = se[lane] + se[lane + 32];
            #pragma unroll
            for (int o = 16; o > 0; o >>= 1)
                v += __shfl_down_sync(0xffffffffu, v, o);
            v = __shfl_sync(0xffffffffu, v, 0);
            float sc = 1.0f / (v + 1e-7f);
            if (lane < 16) {
                float a = se[r * 16 + lane] * sc;
                sa[lane] = a;
                outW[(size_t)bt * 64 + r * 16 + lane] = a;
            }
        }
        __syncthreads();

        {
            int f = tid & 255, h = tid >> 8;
            const float* xt = xbuf + cur * 4096;
            float s = 0.0f;
            #pragma unroll
            for (int j = 0; j < 8; j++)
                s = fmaf(sa[h * 8 + j], xt[(h * 8 + j) * 256 + f], s);
            attp[h * 256 + f] = s;
        }
        __syncthreads();

        if (tid < 256) {
            float a2 = attp[tid] + attp[256 + tid];
            attq[r * 256 + tid] = a2;
            uint32_t la = attq_a + (r * 256 + tid) * 4;
            #pragma unroll
            for (uint32_t q = 0; q < 4; q++)
                if (q != r) st_remote(mapa_u32(la, q), a2);
        }
        cluster_sync();   // all attended partials visible

        // --- phase 4: combine, ctx update, outputs (own f quarter) ---
        if (tid < 256) {
            float att = attq[tid] + attq[256 + tid] +
                        attq[512 + tid] + attq[768 + tid];
            float nc = ctx[tid] + att;      // DISCOUNT = 1
            ctx[tid] = nc;
            if ((uint32_t)(tid >> 6) == r) {
                outO[(size_t)bt * 256 + tid] = att;
                outC[(size_t)bt * 256 + tid] = nc;
            }
        }
        __syncthreads();
    }
}

// =====================================================================
// Launch
// =====================================================================
extern "C" void kernel_launch(void* const* d_in, const int* in_sizes, int n_in,
                              void* d_out, int out_size)
{
    const float* x   = (const float*)d_in[0];  // [B,T,S,F]
    const float* W   = (const float*)d_in[1];  // [F,F]
    const float* Wc  = (const float*)d_in[2];  // [F,F]
    const float* Wl  = (const float*)d_in[3];  // [F]
    const float* Wlc = (const float*)d_in[4];  // [F]
    const float* bl  = (const float*)d_in[5];  // [1]
    const float* bb  = (const float*)d_in[6];  // [F]
    const float* u   = (const float*)d_in[7];  // [F]
    float* out = (float*)d_out;

    // 1) hoisted GEMM: uit = x @ W (+ fused xwl = x @ W_l)
    gemm_uit_kernel<<<MROWS / 128, 512>>>(x, W, Wl);

    // 2) cluster scan: 4 CTAs per batch element
    const size_t smem_bytes = (size_t)SMEM_FLOATS * sizeof(float);
    cudaFuncSetAttribute(scan_cluster_kernel,
                         cudaFuncAttributeMaxDynamicSharedMemorySize,
                         (int)smem_bytes);
    scan_cluster_kernel<<<NB * 4, 512, smem_bytes>>>(x, Wc, Wlc, bl, bb, u, out);
}

// round 7
// speedup vs baseline: 4.3172x; 2.2945x over previous
#include <cuda_runtime.h>
#include <cuda_bf16.h>
#include <cstdint>

// Problem dims (fixed by reference)
#define NB 32
#define NT 128
#define NS 64
#define NF 256
#define MROWS (NB*NT*NS)   // 262144 rows of x flattened as [M, F]

// tcgen05 only exists on the sm_103a feature target; the harness also runs a
// plain compute_103 pass, which must compile a fallback.
#if defined(__CUDA_ARCH__) && (__CUDA_ARCH__ == 1030) && defined(__CUDA_ARCH_FEAT_SM103_ALL)
#define HAS_TCGEN05 1
#else
#define HAS_TCGEN05 0
#endif

// Scratch (device globals: allocation-free rule)
__device__ float g_uit[(size_t)MROWS * NF];  // 256 MiB: x @ W
__device__ float g_xwl[MROWS];               // x @ W_l
// Pre-swizzled bf16 SMEM images of W (hi/lo), per K-half: [2][64 KiB]
__device__ __align__(16) unsigned char g_Bhi[2 * 65536];
__device__ __align__(16) unsigned char g_Blo[2 * 65536];

// ---------------------------------------------------------------------
// PTX helpers (arch-neutral)
// ---------------------------------------------------------------------
__device__ __forceinline__ uint32_t smem_u32(const void* p) {
    uint32_t a;
    asm("{ .reg .u64 t; cvta.to.shared.u64 t, %1; cvt.u32.u64 %0, t; }"
        : "=r"(a) : "l"(p));
    return a;
}
__device__ __forceinline__ uint32_t mapa_u32(uint32_t a, uint32_t rank) {
    uint32_t o;
    asm("mapa.shared::cluster.u32 %0, %1, %2;" : "=r"(o) : "r"(a), "r"(rank));
    return o;
}
__device__ __forceinline__ void st_remote(uint32_t a, float v) {
    asm volatile("st.shared::cluster.f32 [%0], %1;" :: "r"(a), "f"(v));
}
__device__ __forceinline__ void cp16(uint32_t s, const void* g) {
    asm volatile("cp.async.cg.shared.global [%0], [%1], 16;" :: "r"(s), "l"(g));
}
__device__ __forceinline__ void cluster_sync() {
    asm volatile("barrier.cluster.arrive.aligned;" ::: "memory");
    asm volatile("barrier.cluster.wait.aligned;"   ::: "memory");
}
__device__ __forceinline__ void mbar_init(uint32_t a, uint32_t cnt) {
    asm volatile("mbarrier.init.shared.b64 [%0], %1;" :: "r"(a), "r"(cnt) : "memory");
}
__device__ __forceinline__ void mbar_wait(uint32_t a, uint32_t parity) {
    asm volatile(
        "{\n\t.reg .pred P1;\n\t"
        "W%=:\n\t"
        "mbarrier.try_wait.parity.acquire.cta.shared::cta.b64 P1, [%0], %1, 0x989680;\n\t"
        "@P1 bra.uni D%=;\n\t"
        "bra.uni W%=;\n\t"
        "D%=:\n\t}"
        :: "r"(a), "r"(parity) : "memory");
}

#if HAS_TCGEN05
__device__ __forceinline__ bool elect_one() {
    uint32_t p;
    asm volatile("{\n\t.reg .pred p;\n\telect.sync _|p, 0xFFFFFFFF;\n\t"
                 "selp.b32 %0, 1, 0, p;\n\t}" : "=r"(p));
    return p != 0;
}
__device__ __forceinline__ uint64_t mkdesc(uint32_t addr) {
    const uint64_t base = (2ull << 61) | (1ull << 46) | (64ull << 32) | (1ull << 16);
    return base | ((uint64_t)(addr >> 4) & 0x3FFF);
}
__device__ __forceinline__ void mma_f16_ss(uint32_t d, uint64_t a, uint64_t b,
                                           uint32_t idesc, bool accum) {
    uint32_t en = accum ? 1u : 0u;
    asm volatile(
        "{\n\t.reg .pred p;\n\tsetp.ne.u32 p, %4, 0;\n\t"
        "tcgen05.mma.cta_group::1.kind::f16 [%0], %1, %2, %3, {%5, %5, %5, %5}, p;\n\t}"
        :: "r"(d), "l"(a), "l"(b), "r"(idesc), "r"(en), "r"(0u) : "memory");
}
__device__ __forceinline__ void tmem_commit(uint32_t mbar) {
    asm volatile(
        "tcgen05.commit.cta_group::1.mbarrier::arrive::one.shared::cluster.b64 [%0];"
        :: "r"(mbar) : "memory");
}
__device__ __forceinline__ void ldtm32(uint32_t* r, uint32_t a) {
    asm volatile(
        "tcgen05.ld.sync.aligned.32x32b.x32.b32 "
        "{%0, %1, %2, %3, %4, %5, %6, %7, "
        " %8, %9, %10, %11, %12, %13, %14, %15, "
        " %16, %17, %18, %19, %20, %21, %22, %23, "
        " %24, %25, %26, %27, %28, %29, %30, %31}, [%32];"
        : "=r"(r[0]),  "=r"(r[1]),  "=r"(r[2]),  "=r"(r[3]),
          "=r"(r[4]),  "=r"(r[5]),  "=r"(r[6]),  "=r"(r[7]),
          "=r"(r[8]),  "=r"(r[9]),  "=r"(r[10]), "=r"(r[11]),
          "=r"(r[12]), "=r"(r[13]), "=r"(r[14]), "=r"(r[15]),
          "=r"(r[16]), "=r"(r[17]), "=r"(r[18]), "=r"(r[19]),
          "=r"(r[20]), "=r"(r[21]), "=r"(r[22]), "=r"(r[23]),
          "=r"(r[24]), "=r"(r[25]), "=r"(r[26]), "=r"(r[27]),
          "=r"(r[28]), "=r"(r[29]), "=r"(r[30]), "=r"(r[31])
        : "r"(a));
}
#endif  // HAS_TCGEN05

// ---------------------------------------------------------------------
// Kernel 0: convert W -> swizzled bf16 hi/lo SMEM images (per K-half).
// B layout for MMA: B[g][f] = W[f][g], K-major blocked atoms (8 rows x 64
// bf16 = 1024 B), atom_off = (g>>3) + (fi>>6)*32, SW128 swizzle.
// ---------------------------------------------------------------------
__global__ void convW_kernel(const float* __restrict__ W)
{
    int id = blockIdx.x * 256 + threadIdx.x;   // grid 256 -> 65536 elems
    int f = id >> 8, g = id & 255;
    float w = W[id];
    __nv_bfloat16 hi = __float2bfloat16(w);
    __nv_bfloat16 lo = __float2bfloat16(w - __bfloat162float(hi));
    int half = f >> 7, fi = f & 127;
    uint32_t off = (uint32_t)((((g >> 3) + (fi >> 6) * 32) << 10)
                              + ((g & 7) << 7) + ((fi & 63) << 1));
    off ^= (off >> 3) & 0x70;
    *(__nv_bfloat16*)&g_Bhi[half * 65536 + off] = hi;
    *(__nv_bfloat16*)&g_Blo[half * 65536 + off] = lo;
}

// ---------------------------------------------------------------------
// Kernel 1: uit = x @ W.
// sm_103a pass: tcgen05 bf16x3 (hi*hi + hi*lo + lo*hi), M-tile 128,
//   N = 2 x 128 (two MMAs per step, D at tmem+0 / tmem+128),
//   K = 256 in two 128-halves. Fused exact fp32 xwl = x @ W_l.
// non-a pass (fallback, never selected on this GPU): R2 FFMA2 SIMT GEMM.
// ---------------------------------------------------------------------
#define GA_HI 0
#define GA_LO 32768
#define GB_HI 65536
#define GB_LO 131072
#define GSMEM_REQ (196608 + 1024)
// kind::f16 idesc: dtype=F32, atype=btype=BF16, N=128 (16<<17), M=128 (8<<24)
#define IDESC_BF16_N128 ((1u<<4) | (1u<<7) | (1u<<10) | (16u<<17) | (8u<<24))

__global__ void __launch_bounds__(512, 1) __cluster_dims__(1, 1, 1)
gemm_tc_kernel(const float* __restrict__ x,
               const float* __restrict__ W,
               const float* __restrict__ Wl)
{
#if HAS_TCGEN05
    extern __shared__ float smf[];
    __shared__ uint32_t s_tmem[1];
    __shared__ __align__(8) unsigned long long s_mbar[1];

    const int tid = threadIdx.x, lane = tid & 31, wid = tid >> 5;
    const int m0 = blockIdx.x * 128;

    uint32_t raw = smem_u32(smf);
    uint32_t abase = (raw + 1023u) & ~1023u;       // 1 KiB aligned base
    char* smb = (char*)smf + (abase - raw);
    float* stage = (float*)smb;

    const uint32_t tptr_a = smem_u32(s_tmem);
    const uint32_t mbar_a = smem_u32(s_mbar);

    if (wid == 0) {
        asm volatile(
            "tcgen05.alloc.cta_group::1.sync.aligned.shared::cta.b32 [%0], %1;"
            :: "r"(tptr_a), "r"(256u) : "memory");
    } else {
        asm volatile("tcgen05.relinquish_alloc_permit.cta_group::1.sync.aligned;");
    }
    if (tid == 0) mbar_init(mbar_a, 1);
    __syncthreads();
    const uint32_t tmem = s_tmem[0];

    float xlacc[8];
    #pragma unroll
    for (int j = 0; j < 8; j++) xlacc[j] = 0.0f;

    #pragma unroll 1
    for (int half = 0; half < 2; half++) {
        // --- cp.async pre-swizzled W images (hi+lo, 128 KiB) ---
        {
            const char* sH = (const char*)g_Bhi + half * 65536;
            const char* sL = (const char*)g_Blo + half * 65536;
            #pragma unroll
            for (int i = tid; i < 4096; i += 512) {
                cp16(abase + GB_HI + i * 16, sH + i * 16);
                cp16(abase + GB_LO + i * 16, sL + i * 16);
            }
            asm volatile("cp.async.commit_group;");
        }
        // --- load x K-half, split to bf16 hi/lo, swizzled STS; fused xwl ---
        {
            const float4 wl4 = *reinterpret_cast<const float4*>(&Wl[half * 128 + 4 * lane]);
            const uint32_t fi = 4u * (uint32_t)lane;
            #pragma unroll
            for (int j = 0; j < 8; j++) {
                int row = wid + 16 * j;
                float4 v = *reinterpret_cast<const float4*>(
                    &x[(size_t)(m0 + row) * 256 + half * 128 + 4 * lane]);
                // exact fp32 xwl partial
                float p = fmaf(v.x, wl4.x, fmaf(v.y, wl4.y,
                          fmaf(v.z, wl4.z, v.w * wl4.w)));
                #pragma unroll
                for (int o = 16; o > 0; o >>= 1)
                    p += __shfl_down_sync(0xffffffffu, p, o);
                if (lane == 0) xlacc[j] += p;
                // bf16 split
                __nv_bfloat16 h0 = __float2bfloat16(v.x);
                __nv_bfloat16 h1 = __float2bfloat16(v.y);
                __nv_bfloat16 h2 = __float2bfloat16(v.z);
                __nv_bfloat16 h3 = __float2bfloat16(v.w);
                __nv_bfloat16 l0 = __float2bfloat16(v.x - __bfloat162float(h0));
                __nv_bfloat16 l1 = __float2bfloat16(v.y - __bfloat162float(h1));
                __nv_bfloat16 l2 = __float2bfloat16(v.z - __bfloat162float(h2));
                __nv_bfloat16 l3 = __float2bfloat16(v.w - __bfloat162float(h3));
                __nv_bfloat162 hA = {h0, h1}, hB = {h2, h3};
                __nv_bfloat162 lA = {l0, l1}, lB = {l2, l3};
                uint2 uh = make_uint2(*(uint32_t*)&hA, *(uint32_t*)&hB);
                uint2 ul = make_uint2(*(uint32_t*)&lA, *(uint32_t*)&lB);
                uint32_t off = (uint32_t)(((row >> 3) + (int)(fi >> 6) * 16) << 10)
                               + ((row & 7) << 7) + ((fi & 63) << 1);
                off ^= (off >> 3) & 0x70;
                *(uint2*)(smb + GA_HI + off) = uh;
                *(uint2*)(smb + GA_LO + off) = ul;
            }
        }
        asm volatile("cp.async.wait_group 0;");
        asm volatile("fence.proxy.async.shared::cta;" ::: "memory");
        __syncthreads();

        // --- issue 48 MMAs (3 terms x 8 K-steps x 2 N-halves), one commit ---
        if (wid == 0 && elect_one()) {
            uint64_t ah = mkdesc(abase + GA_HI);
            uint64_t al = mkdesc(abase + GA_LO);
            uint64_t bh = mkdesc(abase + GB_HI);
            uint64_t bl = mkdesc(abase + GB_LO);
            uint64_t Ad[3] = {ah, ah, al};
            uint64_t Bd[3] = {bh, bl, bh};
            #pragma unroll
            for (int t = 0; t < 3; t++) {
                #pragma unroll
                for (int k = 0; k < 8; k++) {
                    uint64_t ao = (uint64_t)((k >> 2) * 1024 + (k & 3) * 2);
                    uint64_t bo = (uint64_t)((k >> 2) * 2048 + (k & 3) * 2);
                    bool accum = !(half == 0 && t == 0 && k == 0);
                    // N-half 0: W cols 0..127 (B atoms 0..15)
                    mma_f16_ss(tmem,       Ad[t] + ao, Bd[t] + bo,
                               IDESC_BF16_N128, accum);
                    // N-half 1: W cols 128..255 (B atoms 16..31 -> +1024 units)
                    mma_f16_ss(tmem + 128, Ad[t] + ao, Bd[t] + bo + 1024,
                               IDESC_BF16_N128, accum);
                }
            }
            tmem_commit(mbar_a);
        }
        mbar_wait(mbar_a, (uint32_t)half);
        __syncthreads();   // buffers reusable next half
    }
    asm volatile("tcgen05.fence::after_thread_sync;" ::: "memory");

    // --- write xwl ---
    if (lane == 0) {
        #pragma unroll
        for (int j = 0; j < 8; j++)
            g_xwl[m0 + wid + 16 * j] = xlacc[j];
    }

    // --- epilogue: TMEM -> SMEM stage (stride 257, conflict-free) ---
    if (wid < 4) {
        int row = wid * 32 + lane;
        #pragma unroll 1
        for (int cb = 0; cb < 8; cb++) {
            uint32_t d[32];
            ldtm32(d, tmem + cb * 32);
            asm volatile("tcgen05.wait::ld.sync.aligned;" ::: "memory");
            #pragma unroll
            for (int c = 0; c < 32; c++)
                stage[row * 257 + cb * 32 + c] = __uint_as_float(d[c]);
        }
    }
    __syncthreads();
    // --- coalesced STG ---
    #pragma unroll
    for (int it = 0; it < 16; it++) {
        int flat = tid + 512 * it;
        int row = flat >> 6;
        int c4 = (flat & 63) * 4;
        const float* s = &stage[row * 257 + c4];
        float4 v = make_float4(s[0], s[1], s[2], s[3]);
        *reinterpret_cast<float4*>(&g_uit[(size_t)(m0 + row) * 256 + c4]) = v;
    }
    __syncthreads();
    if (wid == 0) {
        asm volatile("tcgen05.dealloc.cta_group::1.sync.aligned.b32 %0, %1;"
                     :: "r"(tmem), "r"(256u));
    }

#else  // ------- fallback: R2 FFMA2 SIMT GEMM (non-a compile pass only) -------
    extern __shared__ float smf[];
    float* Asf = smf;                 // [16][132]
    float* Bsf = smf + 16 * 132;      // [16][256]

    const int tid = threadIdx.x;
    const int m0  = blockIdx.x * 128;
    const int tx  = tid & 31;
    const int ty  = tid >> 5;
    const int mb  = ty * 8;
    const int nb  = tx * 8;

    unsigned long long acc[8][4];
    #pragma unroll
    for (int i = 0; i < 8; i++)
        #pragma unroll
        for (int j = 0; j < 4; j++) acc[i][j] = 0ULL;

    float xl = 0.0f;

    for (int k0 = 0; k0 < 256; k0 += 16) {
        {
            int row = tid >> 2;
            int c4  = (tid & 3) * 4;
            float4 v = *reinterpret_cast<const float4*>(
                &x[(size_t)(m0 + row) * 256 + k0 + c4]);
            Asf[(c4 + 0) * 132 + row] = v.x;
            Asf[(c4 + 1) * 132 + row] = v.y;
            Asf[(c4 + 2) * 132 + row] = v.z;
            Asf[(c4 + 3) * 132 + row] = v.w;
        }
        #pragma unroll
        for (int p = 0; p < 2; p++) {
            int fid = tid + p * 512;
            int row = fid >> 6;
            int col = (fid & 63) * 4;
            float4 v = *reinterpret_cast<const float4*>(
                &W[(size_t)(k0 + row) * 256 + col]);
            *reinterpret_cast<float4*>(&Bsf[row * 256 + col]) = v;
        }
        __syncthreads();

        #pragma unroll
        for (int kk = 0; kk < 16; kk++) {
            float4 a0 = *reinterpret_cast<const float4*>(&Asf[kk * 132 + mb]);
            float4 a1 = *reinterpret_cast<const float4*>(&Asf[kk * 132 + mb + 4]);
            ulonglong2 b01 = *reinterpret_cast<const ulonglong2*>(&Bsf[kk * 256 + nb]);
            ulonglong2 b23 = *reinterpret_cast<const ulonglong2*>(&Bsf[kk * 256 + nb + 4]);
            float av[8] = {a0.x, a0.y, a0.z, a0.w, a1.x, a1.y, a1.z, a1.w};
            unsigned long long bv[4] = {b01.x, b01.y, b23.x, b23.y};
            #pragma unroll
            for (int i = 0; i < 8; i++) {
                unsigned long long a2;
                asm("mov.b64 %0, {%1, %1};" : "=l"(a2) : "f"(av[i]));
                #pragma unroll
                for (int j = 0; j < 4; j++) {
                    asm("fma.rn.f32x2 %0, %1, %2, %0;"
                        : "+l"(acc[i][j]) : "l"(a2), "l"(bv[j]));
                }
            }
        }
        if (tid < 128) {
            #pragma unroll
            for (int kk = 0; kk < 16; kk++)
                xl = fmaf(Asf[kk * 132 + tid], Wl[k0 + kk], xl);
        }
        __syncthreads();
    }

    #pragma unroll
    for (int i = 0; i < 8; i++) {
        size_t row = (size_t)(m0 + mb + i);
        float2 p0 = *reinterpret_cast<float2*>(&acc[i][0]);
        float2 p1 = *reinterpret_cast<float2*>(&acc[i][1]);
        float2 p2 = *reinterpret_cast<float2*>(&acc[i][2]);
        float2 p3 = *reinterpret_cast<float2*>(&acc[i][3]);
        float4 o0 = make_float4(p0.x, p0.y, p1.x, p1.y);
        float4 o1 = make_float4(p2.x, p2.y, p3.x, p3.y);
        *reinterpret_cast<float4*>(&g_uit[row * 256 + nb])     = o0;
        *reinterpret_cast<float4*>(&g_uit[row * 256 + nb + 4]) = o1;
    }
    if (tid < 128) g_xwl[m0 + tid] = xl;
#endif
}

// =====================================================================
// Kernel 2: cluster scan (4 CTAs / batch elem). 2 cluster_syncs per step:
// unnormalized attended partials + denominators exchanged together.
// =====================================================================
#define OFF_WCQ   0
#define OFF_UBUF  16384          // 2 x 4096
#define OFF_XBUF  (OFF_UBUF + 8192)
#define OFF_CTX   (OFF_XBUF + 8192)
#define OFF_CVEC  (OFF_CTX + 256)
#define OFF_BIAS  (OFF_CVEC + 256)
#define OFF_U     (OFF_BIAS + 256)
#define OFF_WLC   (OFF_U + 256)
#define OFF_PART  (OFF_WLC + 256)
#define OFF_ATTP  (OFF_PART + 512)
#define OFF_ATTQ  (OFF_ATTP + 512)   // 4 x 256
#define OFF_SE16  (OFF_ATTQ + 1024)  // 16
#define OFF_DEN   (OFF_SE16 + 16)    // 4 (+pad)
#define OFF_SL    (OFF_DEN + 8)      // 16
#define SMEM_FLOATS (OFF_SL + 16)

__global__ void __launch_bounds__(512, 1) __cluster_dims__(4, 1, 1)
scan_cluster_kernel(const float* __restrict__ x,
                    const float* __restrict__ Wc,
                    const float* __restrict__ Wlc,
                    const float* __restrict__ blp,
                    const float* __restrict__ bias,
                    const float* __restrict__ u,
                    float* __restrict__ out)
{
    extern __shared__ float sm[];
    float* wcq  = sm + OFF_WCQ;
    float* ubuf = sm + OFF_UBUF;
    float* xbuf = sm + OFF_XBUF;
    float* ctx  = sm + OFF_CTX;
    float* cvec = sm + OFF_CVEC;
    float* sbias= sm + OFF_BIAS;
    float* su   = sm + OFF_U;
    float* swlc = sm + OFF_WLC;
    float* part = sm + OFF_PART;
    float* attp = sm + OFF_ATTP;
    float* attq = sm + OFF_ATTQ;
    float* se16 = sm + OFF_SE16;
    float* den  = sm + OFF_DEN;
    float* sl   = sm + OFF_SL;

    const int tid  = threadIdx.x;
    const int lane = tid & 31;
    const int wid  = tid >> 5;
    const uint32_t r = (uint32_t)(blockIdx.x & 3);   // cluster rank
    const int b = blockIdx.x >> 2;

    const uint32_t ubuf_a = smem_u32(ubuf);
    const uint32_t xbuf_a = smem_u32(xbuf);
    const uint32_t cvec_a = smem_u32(cvec);
    const uint32_t attq_a = smem_u32(attq);
    const uint32_t den_a  = smem_u32(den);

    // --- init: Wc quarter (columns [r*64, r*64+64)), consts, ctx=0 ---
    for (int i = tid; i < 4096; i += 512) {
        int f  = i >> 4;
        int c4 = (i & 15) << 2;
        float4 v = *reinterpret_cast<const float4*>(
            &Wc[(size_t)f * 256 + r * 64 + c4]);
        *reinterpret_cast<float4*>(&wcq[f * 64 + c4]) = v;
    }
    if (tid < 256) {
        ctx[tid]   = 0.0f;
        sbias[tid] = bias[tid];
        su[tid]    = u[tid];
        swlc[tid]  = Wlc[tid];
    }
    const float bl0 = blp[0];

    float* outO = out;
    float* outC = out + (size_t)NB * NT * NF;
    float* outW = out + (size_t)2 * NB * NT * NF;

    // prefetch tile 0 (own 16 sentences of uit and x)
    {
        size_t base = ((size_t)(b * NT) * NS + r * 16) * NF;
        const float4* gu = reinterpret_cast<const float4*>(g_uit + base);
        const float4* gx = reinterpret_cast<const float4*>(x + base);
        for (int i = tid; i < 1024; i += 512) {
            cp16(ubuf_a + i * 16, gu + i);
            cp16(xbuf_a + i * 16, gx + i);
        }
        asm volatile("cp.async.commit_group;");
    }
    __syncthreads();
    cluster_sync();

    for (int t = 0; t < NT; t++) {
        const int bt = b * NT + t;
        const int cur = t & 1;

        // --- prefetch tile t+1 ---
        if (t + 1 < NT) {
            size_t base = ((size_t)(bt + 1) * NS + r * 16) * NF;
            const float4* gu = reinterpret_cast<const float4*>(g_uit + base);
            const float4* gx = reinterpret_cast<const float4*>(x + base);
            uint32_t ub = ubuf_a + (uint32_t)(cur ^ 1) * 16384;
            uint32_t xb = xbuf_a + (uint32_t)(cur ^ 1) * 16384;
            for (int i = tid; i < 1024; i += 512) {
                cp16(ub + i * 16, gu + i);
                cp16(xb + i * 16, gx + i);
            }
        }
        asm volatile("cp.async.commit_group;");

        float xwl_v = 0.0f;
        if (wid == 2 && lane < 16)
            xwl_v = __ldg(&g_xwl[(size_t)bt * NS + r * 16 + lane]);

        // --- phase 1: matvec partials for own 64 outputs ---
        {
            int g = tid & 63, p = tid >> 6;
            int f0 = p * 32;
            float s0 = 0.0f, s1 = 0.0f;
            #pragma unroll
            for (int i = 0; i < 32; i += 2) {
                s0 = fmaf(ctx[f0 + i],     wcq[(f0 + i) * 64 + g],     s0);
                s1 = fmaf(ctx[f0 + i + 1], wcq[(f0 + i + 1) * 64 + g], s1);
            }
            part[p * 64 + g] = s0 + s1;
        }
        __syncthreads();

        if (tid < 64) {
            float s = 0.0f;
            #pragma unroll
            for (int p = 0; p < 8; p++) s += part[p * 64 + tid];
            cvec[r * 64 + tid] = s;
            uint32_t la = cvec_a + (r * 64 + tid) * 4;
            #pragma unroll
            for (uint32_t q = 0; q < 4; q++)
                if (q != r) st_remote(mapa_u32(la, q), s);
        } else if (wid == 2) {
            float gp = 0.0f;
            #pragma unroll
            for (int i = 0; i < 8; i++)
                gp = fmaf(ctx[lane + i * 32], swlc[lane + i * 32], gp);
            #pragma unroll
            for (int o = 16; o > 0; o >>= 1)
                gp += __shfl_down_sync(0xffffffffu, gp, o);
            gp = __shfl_sync(0xffffffffu, gp, 0);
            if (lane < 16) {
                float lg = gp + bl0 + xwl_v;
                sl[lane] = 1.0f / (1.0f + __expf(-lg));
            }
        }

        asm volatile("cp.async.wait_group 1;");
        cluster_sync();   // cvec + sl visible

        // --- phase 2: tanh + ait + exp (unnormalized), own 16 sentences ---
        {
            float l = sl[wid], oml = 1.0f - l;
            const float* ut = ubuf + cur * 4096 + wid * 256;
            float acc = 0.0f;
            #pragma unroll
            for (int i = 0; i < 8; i++) {
                int f = lane + i * 32;
                float arg = fmaf(l, ut[f], fmaf(oml, cvec[f], sbias[f]));
                float e2 = __expf(2.0f * arg);
                float th = 1.0f - __fdividef(2.0f, e2 + 1.0f);
                acc = fmaf(th, su[f], acc);
            }
            #pragma unroll
            for (int o = 16; o > 0; o >>= 1)
                acc += __shfl_down_sync(0xffffffffu, acc, o);
            if (lane == 0) se16[wid] = __expf(acc);
        }
        __syncthreads();

        // --- phase 3: unnormalized attended partials + denom, one exchange ---
        {
            int f = tid & 255, h = tid >> 8;
            const float* xt = xbuf + cur * 4096;
            float s = 0.0f;
            #pragma unroll
            for (int j = 0; j < 8; j++)
                s = fmaf(se16[h * 8 + j], xt[(h * 8 + j) * 256 + f], s);
            attp[h * 256 + f] = s;
        }
        __syncthreads();

        if (tid < 256) {
            float a2 = attp[tid] + attp[256 + tid];
            attq[r * 256 + tid] = a2;
            uint32_t la = attq_a + (r * 256 + tid) * 4;
            #pragma unroll
            for (uint32_t q = 0; q < 4; q++)
                if (q != r) st_remote(mapa_u32(la, q), a2);
        } else if (wid == 8) {
            float v = (lane < 16) ? se16[lane] : 0.0f;
            #pragma unroll
            for (int o = 8; o > 0; o >>= 1)
                v += __shfl_down_sync(0xffffffffu, v, o);
            if (lane == 0) {
                den[r] = v;
                uint32_t la = den_a + r * 4;
                #pragma unroll
                for (uint32_t q = 0; q < 4; q++)
                    if (q != r) st_remote(mapa_u32(la, q), v);
            }
        }
        cluster_sync();   // all attended partials + denominators visible

        // --- phase 4: normalize, ctx update, outputs ---
        {
            float dsum = den[0] + den[1] + den[2] + den[3] + 1e-7f;
            float inv = 1.0f / dsum;
            if (tid < 256) {
                float att = (attq[tid] + attq[256 + tid] +
                             attq[512 + tid] + attq[768 + tid]) * inv;
                float nc = ctx[tid] + att;      // DISCOUNT = 1
                ctx[tid] = nc;
                if ((uint32_t)(tid >> 6) == r) {
                    outO[(size_t)bt * 256 + tid] = att;
                    outC[(size_t)bt * 256 + tid] = nc;
                }
            } else if (wid == 8 && lane < 16) {
                outW[(size_t)bt * 64 + r * 16 + lane] = se16[lane] * inv;
            }
        }
        __syncthreads();
    }
}

// =====================================================================
// Launch
// =====================================================================
extern "C" void kernel_launch(void* const* d_in, const int* in_sizes, int n_in,
                              void* d_out, int out_size)
{
    const float* x   = (const float*)d_in[0];  // [B,T,S,F]
    const float* W   = (const float*)d_in[1];  // [F,F]
    const float* Wc  = (const float*)d_in[2];  // [F,F]
    const float* Wl  = (const float*)d_in[3];  // [F]
    const float* Wlc = (const float*)d_in[4];  // [F]
    const float* bl  = (const float*)d_in[5];  // [1]
    const float* bb  = (const float*)d_in[6];  // [F]
    const float* u   = (const float*)d_in[7];  // [F]
    float* out = (float*)d_out;

    // 0) W -> pre-swizzled bf16 hi/lo images
    convW_kernel<<<256, 256>>>(W);

    // 1) GEMM: uit = x @ W (+ fused xwl = x @ W_l)
    cudaFuncSetAttribute(gemm_tc_kernel,
                         cudaFuncAttributeMaxDynamicSharedMemorySize,
                         GSMEM_REQ);
    gemm_tc_kernel<<<MROWS / 128, 512, GSMEM_REQ>>>(x, W, Wl);

    // 2) cluster scan: 4 CTAs per batch element
    const size_t smem_bytes = (size_t)SMEM_FLOATS * sizeof(float);
    cudaFuncSetAttribute(scan_cluster_kernel,
                         cudaFuncAttributeMaxDynamicSharedMemorySize,
                         (int)smem_bytes);
    scan_cluster_kernel<<<NB * 4, 512, smem_bytes>>>(x, Wc, Wlc, bl, bb, u, out);
}